// round 8
// baseline (speedup 1.0000x reference)
#include <cuda_runtime.h>
#include <cuda_bf16.h>
#include <math.h>
#include <stdint.h>

#define L 16384
#define D 1024
#define ADIM 1024

#define BM 128
#define BN 128
#define BK 32
#define NCH (D / BK)               // 32
#define STAGES 3

#define TILEB (BM * BK * 2)        // 8192 B per 128x32 bf16 tile (64 phys rows x 128B)
#define OFF_AH 0
#define OFF_AL (TILEB)
#define OFF_BH (2 * TILEB)
#define OFF_BL (3 * TILEB)
#define STAGEB (4 * TILEB)         // 32768
#define SMEM_TOTAL (STAGES * STAGEB) // 98304 -> 2 CTAs/SM

// ---------------------------------------------------------------------------
// Device scratch
// ---------------------------------------------------------------------------
__device__ __nv_bfloat16 g_hA[(size_t)L * D];
__device__ __nv_bfloat16 g_lA[(size_t)L * D];
__device__ __nv_bfloat16 g_hB[(size_t)ADIM * D];
__device__ __nv_bfloat16 g_lB[(size_t)ADIM * D];
__device__ float g_c[ADIM];
__device__ float g_beta[L];
__device__ unsigned g_maxbits;
__device__ float g_sumexp;

// ---------------------------------------------------------------------------
// helpers
// ---------------------------------------------------------------------------
__device__ __forceinline__ uint32_t smem_u32(const void* p) {
    uint32_t a;
    asm("{ .reg .u64 t; cvta.to.shared.u64 t, %1; cvt.u32.u64 %0, t; }" : "=r"(a) : "l"(p));
    return a;
}
__device__ __forceinline__ void cpa16(uint32_t dst, const void* src) {
    asm volatile("cp.async.cg.shared.global [%0], [%1], 16;" :: "r"(dst), "l"(src));
}
__device__ __forceinline__ void cpa_commit() {
    asm volatile("cp.async.commit_group;");
}
__device__ __forceinline__ void cpa_wait1() {
    asm volatile("cp.async.wait_group 1;" ::: "memory");
}
__device__ __forceinline__ void cpa_wait0() {
    asm volatile("cp.async.wait_group 0;" ::: "memory");
}
__device__ __forceinline__ void ldm4(uint32_t* r, uint32_t addr) {
    asm volatile("ldmatrix.sync.aligned.m8n8.x4.shared.b16 {%0,%1,%2,%3}, [%4];"
                 : "=r"(r[0]), "=r"(r[1]), "=r"(r[2]), "=r"(r[3]) : "r"(addr));
}
__device__ __forceinline__ void mma16816(float* d, const uint32_t* a, uint32_t b0, uint32_t b1) {
    asm volatile("mma.sync.aligned.m16n8k16.row.col.f32.bf16.bf16.f32 "
                 "{%0,%1,%2,%3}, {%4,%5,%6,%7}, {%8,%9}, {%0,%1,%2,%3};"
                 : "+f"(d[0]), "+f"(d[1]), "+f"(d[2]), "+f"(d[3])
                 : "r"(a[0]), "r"(a[1]), "r"(a[2]), "r"(a[3]), "r"(b0), "r"(b1));
}
__device__ __forceinline__ float tanh_fast(float x) {
    float e, r;
    asm("ex2.approx.f32 %0, %1;" : "=f"(e) : "f"(x * 2.88539008177792681f));
    asm("rcp.approx.f32 %0, %1;" : "=f"(r) : "f"(e + 1.0f));
    return fmaf(-2.0f, r, 1.0f);
}
__device__ __forceinline__ unsigned enc_f(float f) {
    unsigned u = __float_as_uint(f);
    return (u & 0x80000000u) ? ~u : (u | 0x80000000u);
}
__device__ __forceinline__ float dec_f(unsigned e) {
    unsigned u = (e & 0x80000000u) ? (e ^ 0x80000000u) : ~e;
    return __uint_as_float(u);
}
__device__ __forceinline__ void split8(const float* src, uint4* hi, uint4* lo) {
    float4 v0 = *(const float4*)src;
    float4 v1 = *(const float4*)(src + 4);
    float vs[8] = {v0.x, v0.y, v0.z, v0.w, v1.x, v1.y, v1.z, v1.w};
    unsigned short hs[8], ls[8];
    #pragma unroll
    for (int k = 0; k < 8; k++) {
        __nv_bfloat16 h = __float2bfloat16(vs[k]);
        hs[k] = __bfloat16_as_ushort(h);
        ls[k] = __bfloat16_as_ushort(__float2bfloat16(vs[k] - __bfloat162float(h)));
    }
    *hi = *(uint4*)hs;
    *lo = *(uint4*)ls;
}

// ---------------------------------------------------------------------------
// K1: c[a] = dot(W_att[a, D:2D], h_t) + b_att[a]  (+ folded init)
// ---------------------------------------------------------------------------
__global__ void k_ctx(const float* __restrict__ W, const float* __restrict__ ht,
                      const float* __restrict__ b, float* __restrict__ out) {
    int a = blockIdx.x;
    if (threadIdx.x < 16) g_beta[a * 16 + threadIdx.x] = 0.0f;
    if (a < 4) out[a * 256 + threadIdx.x] = 0.0f;
    if (a == 0 && threadIdx.x == 0) { g_maxbits = 0u; g_sumexp = 0.0f; }

    const float* w = W + (size_t)a * (2 * D) + D;
    float s = 0.0f;
    for (int k = threadIdx.x; k < D; k += 256) s = fmaf(w[k], ht[k], s);
    __shared__ float red[8];
    #pragma unroll
    for (int o = 16; o > 0; o >>= 1) s += __shfl_down_sync(0xffffffffu, s, o);
    if ((threadIdx.x & 31) == 0) red[threadIdx.x >> 5] = s;
    __syncthreads();
    if (threadIdx.x == 0) {
        float t = 0.0f;
        #pragma unroll
        for (int i = 0; i < 8; i++) t += red[i];
        g_c[a] = t + b[a];
    }
}

// ---------------------------------------------------------------------------
// K2a: h_i -> (hi, lo) bf16 with 16B stores
// ---------------------------------------------------------------------------
__global__ void __launch_bounds__(256) k_conv_h(const float* __restrict__ h) {
    size_t i = ((size_t)blockIdx.x * 256 + threadIdx.x) * 16;
    uint4 hv0, lv0, hv1, lv1;
    split8(h + i, &hv0, &lv0);
    split8(h + i + 8, &hv1, &lv1);
    *(uint4*)(g_hA + i) = hv0;  *(uint4*)(g_hA + i + 8) = hv1;
    *(uint4*)(g_lA + i) = lv0;  *(uint4*)(g_lA + i + 8) = lv1;
}

// ---------------------------------------------------------------------------
// K2b: W1 -> (hi, lo) bf16 with 16B stores
// ---------------------------------------------------------------------------
__global__ void __launch_bounds__(256) k_conv_w(const float* __restrict__ W) {
    int q = blockIdx.x * 256 + threadIdx.x;
    int a = q >> 6, c = (q & 63) * 16;
    const float* src = W + (size_t)a * (2 * D) + c;
    size_t o = (size_t)a * D + c;
    uint4 hv0, lv0, hv1, lv1;
    split8(src, &hv0, &lv0);
    split8(src + 8, &hv1, &lv1);
    *(uint4*)(g_hB + o) = hv0;  *(uint4*)(g_hB + o + 8) = hv1;
    *(uint4*)(g_lB + o) = lv0;  *(uint4*)(g_lB + o + 8) = lv1;
}

// ---------------------------------------------------------------------------
// K3: HMMA GEMM, BK=32, paired-row swizzle, 3-stage cp.async, 2 CTAs/SM
//   Physical tile: 64 rows x 128B; logical row r -> (p = r>>1, half = r&1)
//   16B chunk cc in 0..7 stored at p*128 + ((cc ^ (p&7)) << 4)
// ---------------------------------------------------------------------------
__global__ void __launch_bounds__(256, 2) k_gemm(const float* __restrict__ u_in) {
    extern __shared__ __align__(128) char smem[];
    const uint32_t sbase = smem_u32(smem);
    const int tid = threadIdx.x;
    const int lane = tid & 31, wid = tid >> 5;
    const int warp_m = wid >> 2, warp_n = wid & 3;
    const int a0 = blockIdx.x * BN;       // a-tile fast
    const int l0 = blockIdx.y * BM;

    // ---- cp.async mapping: thread -> logical row (tid>>1), 2 chunks (tid&1)*2+{0,1}
    const int crow = tid >> 1;                       // 0..127
    const int cb = (tid & 1) * 2;                    // chunk base 0 or 2
    const uint32_t p_ = (uint32_t)(crow >> 1);
    const uint32_t ps = p_ & 7;
    const uint32_t ccb = (uint32_t)(crow & 1) * 4;
    const uint32_t d0 = p_ * 128 + (((ccb + cb) ^ ps) << 4);
    const uint32_t d1 = p_ * 128 + (((ccb + cb + 1) ^ ps) << 4);
    const size_t srcoff = ((size_t)crow * D + cb * 8) * 2;  // bytes
    const char* pAh = (const char*)g_hA + (size_t)l0 * D * 2 + srcoff;
    const char* pAl = (const char*)g_lA + (size_t)l0 * D * 2 + srcoff;
    const char* pBh = (const char*)g_hB + (size_t)a0 * D * 2 + srcoff;
    const char* pBl = (const char*)g_lB + (size_t)a0 * D * 2 + srcoff;

    // ---- ldmatrix addressing (logical row -> physical paired-row swizzle)
    uint32_t aP[4], aC[4], aS[4];
    #pragma unroll
    for (int i = 0; i < 4; i++) {
        int r = warp_m * 64 + i * 16 + (lane & 15);
        aP[i] = (uint32_t)(r >> 1) * 128;
        aC[i] = (uint32_t)(r & 1) * 4;
        aS[i] = (uint32_t)(r >> 1) & 7;
    }
    const uint32_t aCh = (uint32_t)(lane >> 4);
    uint32_t bP[2], bC[2], bS[2];
    #pragma unroll
    for (int pp = 0; pp < 2; pp++) {
        int r = warp_n * 32 + pp * 16 + (lane & 7) + ((lane >> 4) & 1) * 8;
        bP[pp] = (uint32_t)(r >> 1) * 128;
        bC[pp] = (uint32_t)(r & 1) * 4;
        bS[pp] = (uint32_t)(r >> 1) & 7;
    }
    const uint32_t bCh = (uint32_t)((lane >> 3) & 1);

    float acc[4][4][4];
    #pragma unroll
    for (int i = 0; i < 4; i++)
        #pragma unroll
        for (int j = 0; j < 4; j++)
            #pragma unroll
            for (int r = 0; r < 4; r++) acc[i][j][r] = 0.0f;

    auto issue = [&](int kc, int st) {
        const uint32_t sb = sbase + (uint32_t)st * STAGEB;
        const size_t ko = (size_t)kc * 64;   // 32 bf16 = 64 bytes per row
        cpa16(sb + OFF_AH + d0, pAh + ko);      cpa16(sb + OFF_AH + d1, pAh + ko + 16);
        cpa16(sb + OFF_AL + d0, pAl + ko);      cpa16(sb + OFF_AL + d1, pAl + ko + 16);
        cpa16(sb + OFF_BH + d0, pBh + ko);      cpa16(sb + OFF_BH + d1, pBh + ko + 16);
        cpa16(sb + OFF_BL + d0, pBl + ko);      cpa16(sb + OFF_BL + d1, pBl + ko + 16);
        cpa_commit();
    };

    issue(0, 0);
    issue(1, 1);

    for (int kc = 0; kc < NCH; kc++) {
        if (kc == NCH - 1) cpa_wait0(); else cpa_wait1();
        __syncthreads();
        if (kc + 2 < NCH) issue(kc + 2, (kc + 2) % STAGES);

        const uint32_t base = sbase + (uint32_t)(kc % STAGES) * STAGEB;
        #pragma unroll
        for (int ks = 0; ks < 2; ks++) {
            uint32_t ah[4][4], al[4][4], bh[4], bl[4];
            const uint32_t ac = (uint32_t)ks * 2 + aCh;
            const uint32_t bc = (uint32_t)ks * 2 + bCh;
            #pragma unroll
            for (int i = 0; i < 4; i++) {
                uint32_t ad = base + aP[i] + (((aC[i] + ac) ^ aS[i]) << 4);
                ldm4(ah[i], ad + OFF_AH);
                ldm4(al[i], ad + OFF_AL);
            }
            #pragma unroll
            for (int pp = 0; pp < 2; pp++) {
                uint32_t bd = base + bP[pp] + (((bC[pp] + bc) ^ bS[pp]) << 4);
                ldm4(bh, bd + OFF_BH);
                ldm4(bl, bd + OFF_BL);
                #pragma unroll
                for (int i = 0; i < 4; i++)
                    #pragma unroll
                    for (int jj = 0; jj < 2; jj++) {
                        const int j = pp * 2 + jj, q = jj * 2;
                        mma16816(acc[i][j], ah[i], bh[q], bh[q + 1]);
                        mma16816(acc[i][j], ah[i], bl[q], bl[q + 1]);
                        mma16816(acc[i][j], al[i], bh[q], bh[q + 1]);
                    }
            }
        }
    }

    // ---- epilogue
    const int gID = lane >> 2, tig = lane & 3;
    float cl[4][2], ul[4][2];
    #pragma unroll
    for (int j = 0; j < 4; j++) {
        const int ag = a0 + warp_n * 32 + j * 8 + 2 * tig;
        cl[j][0] = g_c[ag];  cl[j][1] = g_c[ag + 1];
        ul[j][0] = u_in[ag]; ul[j][1] = u_in[ag + 1];
    }
    #pragma unroll
    for (int i = 0; i < 4; i++) {
        float sA = 0.0f, sB = 0.0f;
        #pragma unroll
        for (int j = 0; j < 4; j++) {
            sA = fmaf(tanh_fast(acc[i][j][0] + cl[j][0]), ul[j][0], sA);
            sA = fmaf(tanh_fast(acc[i][j][1] + cl[j][1]), ul[j][1], sA);
            sB = fmaf(tanh_fast(acc[i][j][2] + cl[j][0]), ul[j][0], sB);
            sB = fmaf(tanh_fast(acc[i][j][3] + cl[j][1]), ul[j][1], sB);
        }
        sA += __shfl_xor_sync(0xffffffffu, sA, 1);
        sA += __shfl_xor_sync(0xffffffffu, sA, 2);
        sB += __shfl_xor_sync(0xffffffffu, sB, 1);
        sB += __shfl_xor_sync(0xffffffffu, sB, 2);
        if (tig == 0) {
            const int r = l0 + warp_m * 64 + i * 16 + gID;
            atomicAdd(&g_beta[r], sA);
            atomicAdd(&g_beta[r + 8], sB);
        }
    }
}

// ---------------------------------------------------------------------------
// K4: softmax stats
// ---------------------------------------------------------------------------
__global__ void k_max() {
    int i = blockIdx.x * 1024 + threadIdx.x;
    float v = g_beta[i];
    #pragma unroll
    for (int o = 16; o > 0; o >>= 1) v = fmaxf(v, __shfl_xor_sync(0xffffffffu, v, o));
    __shared__ float r[32];
    if ((threadIdx.x & 31) == 0) r[threadIdx.x >> 5] = v;
    __syncthreads();
    if (threadIdx.x < 32) {
        v = r[threadIdx.x];
        #pragma unroll
        for (int o = 16; o > 0; o >>= 1) v = fmaxf(v, __shfl_xor_sync(0xffffffffu, v, o));
        if (threadIdx.x == 0) atomicMax(&g_maxbits, enc_f(v));
    }
}
__global__ void k_sum() {
    int i = blockIdx.x * 1024 + threadIdx.x;
    float mx = dec_f(g_maxbits);
    float v = expf(g_beta[i] - mx);
    #pragma unroll
    for (int o = 16; o > 0; o >>= 1) v += __shfl_xor_sync(0xffffffffu, v, o);
    __shared__ float r[32];
    if ((threadIdx.x & 31) == 0) r[threadIdx.x >> 5] = v;
    __syncthreads();
    if (threadIdx.x < 32) {
        v = r[threadIdx.x];
        #pragma unroll
        for (int o = 16; o > 0; o >>= 1) v += __shfl_xor_sync(0xffffffffu, v, o);
        if (threadIdx.x == 0) atomicAdd(&g_sumexp, v);
    }
}

// ---------------------------------------------------------------------------
// K5: s[d] = sum_l alpha_l * h_i[l][d]
// ---------------------------------------------------------------------------
#define OROWS 128
__global__ void __launch_bounds__(256) k_out(const float* __restrict__ h_i,
                                             float* __restrict__ out) {
    __shared__ float w[OROWS];
    int l0 = blockIdx.x * OROWS;
    int tid = threadIdx.x;
    float mx = dec_f(g_maxbits), se = g_sumexp;
    if (tid < OROWS) w[tid] = expf(g_beta[l0 + tid] - mx) / se;
    __syncthreads();
    float acc[4] = {0.0f, 0.0f, 0.0f, 0.0f};
    for (int l = 0; l < OROWS; l++) {
        float wl = w[l];
        const float* rp = h_i + (size_t)(l0 + l) * D;
        #pragma unroll
        for (int j = 0; j < 4; j++)
            acc[j] = fmaf(wl, rp[tid + j * 256], acc[j]);
    }
    #pragma unroll
    for (int j = 0; j < 4; j++) atomicAdd(&out[tid + j * 256], acc[j]);
}

// ---------------------------------------------------------------------------
extern "C" void kernel_launch(void* const* d_in, const int* in_sizes, int n_in,
                              void* d_out, int out_size) {
    const float* h_i = (const float*)d_in[0];
    const float* h_t = (const float*)d_in[1];
    const float* W   = (const float*)d_in[2];
    const float* b   = (const float*)d_in[3];
    const float* u   = (const float*)d_in[4];
    float* out = (float*)d_out;

    static bool attr_set = false;
    if (!attr_set) {
        cudaFuncSetAttribute(k_gemm, cudaFuncAttributeMaxDynamicSharedMemorySize, SMEM_TOTAL);
        attr_set = true;
    }

    // launch order keeps k_gemm 4th so the ncu -s/-c window lands on it
    k_ctx<<<ADIM, 256>>>(W, h_t, b, out);
    k_conv_h<<<(int)(((size_t)L * D) / 4096), 256>>>(h_i);
    k_conv_w<<<(ADIM * D / 16) / 256, 256>>>(W);
    dim3 g(ADIM / BN, L / BM);
    k_gemm<<<g, 256, SMEM_TOTAL>>>(u);
    k_max<<<16, 1024>>>();
    k_sum<<<16, 1024>>>();
    k_out<<<L / OROWS, 256>>>(h_i, out);
}

// round 9
// speedup vs baseline: 1.1923x; 1.1923x over previous
#include <cuda_runtime.h>
#include <cuda_bf16.h>
#include <math.h>
#include <stdint.h>

#define L 16384
#define D 1024
#define ADIM 1024

#define BM 128
#define BN 128
#define BK 64
#define NCH (D / BK)               // 16
#define STAGES 3

#define TILEB (BM * BK * 2)        // 16384 B per 128x64 bf16 tile
#define OFF_AH 0
#define OFF_AL (TILEB)
#define OFF_BH (2 * TILEB)
#define OFF_BL (3 * TILEB)
#define STAGEB (4 * TILEB)         // 65536
#define SMEM_TOTAL (STAGES * STAGEB) // 196608

// ---------------------------------------------------------------------------
// Device scratch
// ---------------------------------------------------------------------------
__device__ __nv_bfloat16 g_hA[(size_t)L * D];
__device__ __nv_bfloat16 g_lA[(size_t)L * D];
__device__ __nv_bfloat16 g_hB[(size_t)ADIM * D];
__device__ __nv_bfloat16 g_lB[(size_t)ADIM * D];
__device__ float g_c[ADIM];
__device__ float g_beta[L];
__device__ unsigned g_maxbits;
__device__ float g_sumexp;

// ---------------------------------------------------------------------------
// helpers
// ---------------------------------------------------------------------------
__device__ __forceinline__ uint32_t smem_u32(const void* p) {
    uint32_t a;
    asm("{ .reg .u64 t; cvta.to.shared.u64 t, %1; cvt.u32.u64 %0, t; }" : "=r"(a) : "l"(p));
    return a;
}
__device__ __forceinline__ void cpa16(uint32_t dst, const void* src) {
    asm volatile("cp.async.cg.shared.global [%0], [%1], 16;" :: "r"(dst), "l"(src));
}
__device__ __forceinline__ void cpa_commit() {
    asm volatile("cp.async.commit_group;");
}
__device__ __forceinline__ void cpa_wait1() {
    asm volatile("cp.async.wait_group 1;" ::: "memory");
}
__device__ __forceinline__ void cpa_wait0() {
    asm volatile("cp.async.wait_group 0;" ::: "memory");
}
__device__ __forceinline__ void ldm4(uint32_t* r, uint32_t addr) {
    asm volatile("ldmatrix.sync.aligned.m8n8.x4.shared.b16 {%0,%1,%2,%3}, [%4];"
                 : "=r"(r[0]), "=r"(r[1]), "=r"(r[2]), "=r"(r[3]) : "r"(addr));
}
__device__ __forceinline__ void mma16816(float* d, const uint32_t* a, uint32_t b0, uint32_t b1) {
    asm volatile("mma.sync.aligned.m16n8k16.row.col.f32.bf16.bf16.f32 "
                 "{%0,%1,%2,%3}, {%4,%5,%6,%7}, {%8,%9}, {%0,%1,%2,%3};"
                 : "+f"(d[0]), "+f"(d[1]), "+f"(d[2]), "+f"(d[3])
                 : "r"(a[0]), "r"(a[1]), "r"(a[2]), "r"(a[3]), "r"(b0), "r"(b1));
}
__device__ __forceinline__ float tanh_fast(float x) {
    float e, r;
    asm("ex2.approx.f32 %0, %1;" : "=f"(e) : "f"(x * 2.88539008177792681f));
    asm("rcp.approx.f32 %0, %1;" : "=f"(r) : "f"(e + 1.0f));
    return fmaf(-2.0f, r, 1.0f);
}
__device__ __forceinline__ unsigned enc_f(float f) {
    unsigned u = __float_as_uint(f);
    return (u & 0x80000000u) ? ~u : (u | 0x80000000u);
}
__device__ __forceinline__ float dec_f(unsigned e) {
    unsigned u = (e & 0x80000000u) ? (e ^ 0x80000000u) : ~e;
    return __uint_as_float(u);
}
__device__ __forceinline__ void split8(const float* src, uint4* hi, uint4* lo) {
    float4 v0 = *(const float4*)src;
    float4 v1 = *(const float4*)(src + 4);
    float vs[8] = {v0.x, v0.y, v0.z, v0.w, v1.x, v1.y, v1.z, v1.w};
    unsigned short hs[8], ls[8];
    #pragma unroll
    for (int k = 0; k < 8; k++) {
        __nv_bfloat16 h = __float2bfloat16(vs[k]);
        hs[k] = __bfloat16_as_ushort(h);
        ls[k] = __bfloat16_as_ushort(__float2bfloat16(vs[k] - __bfloat162float(h)));
    }
    *hi = *(uint4*)hs;
    *lo = *(uint4*)ls;
}

// ---------------------------------------------------------------------------
// K1: c[a] = dot(W_att[a, D:2D], h_t) + b_att[a]  (+ folded init)
// ---------------------------------------------------------------------------
__global__ void k_ctx(const float* __restrict__ W, const float* __restrict__ ht,
                      const float* __restrict__ b, float* __restrict__ out) {
    int a = blockIdx.x;
    if (threadIdx.x < 16) g_beta[a * 16 + threadIdx.x] = 0.0f;
    if (a < 4) out[a * 256 + threadIdx.x] = 0.0f;
    if (a == 0 && threadIdx.x == 0) { g_maxbits = 0u; g_sumexp = 0.0f; }

    const float* w = W + (size_t)a * (2 * D) + D;
    float s = 0.0f;
    for (int k = threadIdx.x; k < D; k += 256) s = fmaf(w[k], ht[k], s);
    __shared__ float red[8];
    #pragma unroll
    for (int o = 16; o > 0; o >>= 1) s += __shfl_down_sync(0xffffffffu, s, o);
    if ((threadIdx.x & 31) == 0) red[threadIdx.x >> 5] = s;
    __syncthreads();
    if (threadIdx.x == 0) {
        float t = 0.0f;
        #pragma unroll
        for (int i = 0; i < 8; i++) t += red[i];
        g_c[a] = t + b[a];
    }
}

// ---------------------------------------------------------------------------
// K2a: h_i -> (hi, lo) bf16; 8 floats/thread, 2M threads for MLP
// ---------------------------------------------------------------------------
__global__ void __launch_bounds__(256) k_conv_h(const float* __restrict__ h) {
    size_t i = ((size_t)blockIdx.x * 256 + threadIdx.x) * 8;
    uint4 hv, lv;
    split8(h + i, &hv, &lv);
    *(uint4*)(g_hA + i) = hv;
    *(uint4*)(g_lA + i) = lv;
}

// ---------------------------------------------------------------------------
// K2b: W1 -> (hi, lo) bf16; 8 floats/thread
// ---------------------------------------------------------------------------
__global__ void __launch_bounds__(256) k_conv_w(const float* __restrict__ W) {
    int q = blockIdx.x * 256 + threadIdx.x;       // 0..131071
    int a = q >> 7, c = (q & 127) * 8;
    const float* src = W + (size_t)a * (2 * D) + c;
    size_t o = (size_t)a * D + c;
    uint4 hv, lv;
    split8(src, &hv, &lv);
    *(uint4*)(g_hB + o) = hv;
    *(uint4*)(g_lB + o) = lv;
}

// ---------------------------------------------------------------------------
// K3: HMMA GEMM (R7 config): BK=64, 3-stage cp.async, single barrier/chunk
// ---------------------------------------------------------------------------
__global__ void __launch_bounds__(256, 1) k_gemm(const float* __restrict__ u_in) {
    extern __shared__ __align__(128) char smem[];
    const uint32_t sbase = smem_u32(smem);
    const int tid = threadIdx.x;
    const int lane = tid & 31, wid = tid >> 5;
    const int warp_m = wid >> 2, warp_n = wid & 3;
    const int a0 = blockIdx.x * BN;       // a-tile fast -> wave shares B in L2
    const int l0 = blockIdx.y * BM;

    const int crow = tid >> 3;
    const int cch = tid & 7;
    const uint32_t swz_ch = (uint32_t)(cch ^ (crow & 7));
    const uint32_t dbase = (uint32_t)crow * 128 + swz_ch * 16;
    const char* pAh = (const char*)(g_hA + ((size_t)(l0 + crow) * D + cch * 8));
    const char* pAl = (const char*)(g_lA + ((size_t)(l0 + crow) * D + cch * 8));
    const char* pBh = (const char*)(g_hB + ((size_t)(a0 + crow) * D + cch * 8));
    const char* pBl = (const char*)(g_lB + ((size_t)(a0 + crow) * D + cch * 8));
    const size_t gstep = (size_t)32 * D * 2;

    uint32_t aRow[4], aSw[4];
    #pragma unroll
    for (int i = 0; i < 4; i++) {
        int r = warp_m * 64 + i * 16 + (lane & 15);
        aRow[i] = (uint32_t)r * 128;
        aSw[i] = (uint32_t)(r & 7);
    }
    const uint32_t aCh = (uint32_t)(lane >> 4);
    uint32_t bRow[2], bSw[2];
    #pragma unroll
    for (int p = 0; p < 2; p++) {
        int r = warp_n * 32 + p * 16 + (lane & 7) + ((lane >> 4) & 1) * 8;
        bRow[p] = (uint32_t)r * 128;
        bSw[p] = (uint32_t)(r & 7);
    }
    const uint32_t bCh = (uint32_t)((lane >> 3) & 1);

    float acc[4][4][4];
    #pragma unroll
    for (int i = 0; i < 4; i++)
        #pragma unroll
        for (int j = 0; j < 4; j++)
            #pragma unroll
            for (int r = 0; r < 4; r++) acc[i][j][r] = 0.0f;

    auto issue = [&](int kc, int st) {
        const uint32_t sb = sbase + (uint32_t)st * STAGEB;
        const size_t ko = (size_t)kc * BK * 2;
        #pragma unroll
        for (int i = 0; i < 4; i++) {
            const size_t go = ko + (size_t)i * gstep;
            const uint32_t doff = dbase + (uint32_t)i * 32 * 128;
            cpa16(sb + OFF_AH + doff, pAh + go);
            cpa16(sb + OFF_AL + doff, pAl + go);
            cpa16(sb + OFF_BH + doff, pBh + go);
            cpa16(sb + OFF_BL + doff, pBl + go);
        }
        cpa_commit();
    };

    issue(0, 0);
    issue(1, 1);

    for (int kc = 0; kc < NCH; kc++) {
        if (kc == NCH - 1) cpa_wait0(); else cpa_wait1();
        __syncthreads();
        if (kc + 2 < NCH) issue(kc + 2, (kc + 2) % STAGES);

        const uint32_t base = sbase + (uint32_t)(kc % STAGES) * STAGEB;
        #pragma unroll
        for (int ks = 0; ks < 4; ks++) {
            uint32_t ah[4][4], al[4][4], bh[2][4], bl[2][4];
            const uint32_t ac = (uint32_t)ks * 2 + aCh;
            const uint32_t bc = (uint32_t)ks * 2 + bCh;
            #pragma unroll
            for (int i = 0; i < 4; i++) {
                uint32_t ad = base + aRow[i] + ((ac ^ aSw[i]) << 4);
                ldm4(ah[i], ad + OFF_AH);
                ldm4(al[i], ad + OFF_AL);
            }
            #pragma unroll
            for (int p = 0; p < 2; p++) {
                uint32_t bd = base + bRow[p] + ((bc ^ bSw[p]) << 4);
                ldm4(bh[p], bd + OFF_BH);
                ldm4(bl[p], bd + OFF_BL);
            }
            #pragma unroll
            for (int i = 0; i < 4; i++)
                #pragma unroll
                for (int j = 0; j < 4; j++) {
                    const int p = j >> 1, q = (j & 1) * 2;
                    mma16816(acc[i][j], ah[i], bh[p][q], bh[p][q + 1]);
                    mma16816(acc[i][j], ah[i], bl[p][q], bl[p][q + 1]);
                    mma16816(acc[i][j], al[i], bh[p][q], bh[p][q + 1]);
                }
        }
    }

    // ---- epilogue
    const int gID = lane >> 2, tig = lane & 3;
    float cl[4][2], ul[4][2];
    #pragma unroll
    for (int j = 0; j < 4; j++) {
        const int ag = a0 + warp_n * 32 + j * 8 + 2 * tig;
        cl[j][0] = g_c[ag];  cl[j][1] = g_c[ag + 1];
        ul[j][0] = u_in[ag]; ul[j][1] = u_in[ag + 1];
    }
    #pragma unroll
    for (int i = 0; i < 4; i++) {
        float sA = 0.0f, sB = 0.0f;
        #pragma unroll
        for (int j = 0; j < 4; j++) {
            sA = fmaf(tanh_fast(acc[i][j][0] + cl[j][0]), ul[j][0], sA);
            sA = fmaf(tanh_fast(acc[i][j][1] + cl[j][1]), ul[j][1], sA);
            sB = fmaf(tanh_fast(acc[i][j][2] + cl[j][0]), ul[j][0], sB);
            sB = fmaf(tanh_fast(acc[i][j][3] + cl[j][1]), ul[j][1], sB);
        }
        sA += __shfl_xor_sync(0xffffffffu, sA, 1);
        sA += __shfl_xor_sync(0xffffffffu, sA, 2);
        sB += __shfl_xor_sync(0xffffffffu, sB, 1);
        sB += __shfl_xor_sync(0xffffffffu, sB, 2);
        if (tig == 0) {
            const int r = l0 + warp_m * 64 + i * 16 + gID;
            atomicAdd(&g_beta[r], sA);
            atomicAdd(&g_beta[r + 8], sB);
        }
    }
}

// ---------------------------------------------------------------------------
// K4: global max of beta
// ---------------------------------------------------------------------------
__global__ void k_max() {
    int i = blockIdx.x * 1024 + threadIdx.x;
    float v = g_beta[i];
    #pragma unroll
    for (int o = 16; o > 0; o >>= 1) v = fmaxf(v, __shfl_xor_sync(0xffffffffu, v, o));
    __shared__ float r[32];
    if ((threadIdx.x & 31) == 0) r[threadIdx.x >> 5] = v;
    __syncthreads();
    if (threadIdx.x < 32) {
        v = r[threadIdx.x];
        #pragma unroll
        for (int o = 16; o > 0; o >>= 1) v = fmaxf(v, __shfl_xor_sync(0xffffffffu, v, o));
        if (threadIdx.x == 0) atomicMax(&g_maxbits, enc_f(v));
    }
}

// ---------------------------------------------------------------------------
// K5: unnormalized s[d] += sum_l exp(beta_l - max) * h_i[l][d]; also sumexp
// ---------------------------------------------------------------------------
#define OROWS 128
__global__ void __launch_bounds__(256) k_out(const float* __restrict__ h_i,
                                             float* __restrict__ out) {
    __shared__ float w[OROWS];
    int l0 = blockIdx.x * OROWS;
    int tid = threadIdx.x;
    float mx = dec_f(g_maxbits);
    if (tid < OROWS) w[tid] = expf(g_beta[l0 + tid] - mx);
    __syncthreads();
    // block sumexp contribution (one atomic per block)
    if (tid < 32) {
        float s = 0.0f;
        #pragma unroll
        for (int k = 0; k < OROWS / 32; k++) s += w[tid + k * 32];
        #pragma unroll
        for (int o = 16; o > 0; o >>= 1) s += __shfl_xor_sync(0xffffffffu, s, o);
        if (tid == 0) atomicAdd(&g_sumexp, s);
    }
    float acc[4] = {0.0f, 0.0f, 0.0f, 0.0f};
    for (int l = 0; l < OROWS; l++) {
        float wl = w[l];
        const float* rp = h_i + (size_t)(l0 + l) * D;
        #pragma unroll
        for (int j = 0; j < 4; j++)
            acc[j] = fmaf(wl, rp[tid + j * 256], acc[j]);
    }
    #pragma unroll
    for (int j = 0; j < 4; j++) atomicAdd(&out[tid + j * 256], acc[j]);
}

// ---------------------------------------------------------------------------
// K6: normalize out by 1/sumexp
// ---------------------------------------------------------------------------
__global__ void k_norm(float* __restrict__ out) {
    float inv = __frcp_rn(g_sumexp);
    out[blockIdx.x * 256 + threadIdx.x] *= inv;
}

// ---------------------------------------------------------------------------
extern "C" void kernel_launch(void* const* d_in, const int* in_sizes, int n_in,
                              void* d_out, int out_size) {
    const float* h_i = (const float*)d_in[0];
    const float* h_t = (const float*)d_in[1];
    const float* W   = (const float*)d_in[2];
    const float* b   = (const float*)d_in[3];
    const float* u   = (const float*)d_in[4];
    float* out = (float*)d_out;

    static bool attr_set = false;
    if (!attr_set) {
        cudaFuncSetAttribute(k_gemm, cudaFuncAttributeMaxDynamicSharedMemorySize, SMEM_TOTAL);
        attr_set = true;
    }

    // k_gemm stays 4th so the ncu window keeps landing on it
    k_ctx<<<ADIM, 256>>>(W, h_t, b, out);
    k_conv_h<<<(int)(((size_t)L * D) / 2048), 256>>>(h_i);
    k_conv_w<<<(ADIM * D / 8) / 256, 256>>>(W);
    dim3 g(ADIM / BN, L / BM);
    k_gemm<<<g, 256, SMEM_TOTAL>>>(u);
    k_max<<<16, 1024>>>();
    k_out<<<L / OROWS, 256>>>(h_i, out);
    k_norm<<<4, 256>>>(out);
}